// round 4
// baseline (speedup 1.0000x reference)
#include <cuda_runtime.h>
#include <cstdint>
#include <math.h>

#define TOKS 512
#define HDIM 1024
#define FDIM 4096
#define NEXP 8
#define SLOT 512
#define SST  36                 // 32 + 4 pad floats per smem row
#define ASTG_F (128 * SST)      // gemm2 A stage floats (4608)
#define BSTG_F (64 * SST)       // 64-row stage floats (2304)

// ---------------- scratch (static device globals) ---------------------------
__device__ float d_xtf[TOKS * HDIM];               // tf32-rounded x (2 MB)
__device__ float d_h[NEXP * SLOT * FDIM];          // tf32-rounded intermediate h
__device__ float d_po2[2 * NEXP * SLOT * HDIM];    // split-K partials
__device__ int   d_count[NEXP];
__device__ int   d_tok[NEXP * SLOT];
__device__ float d_mult[NEXP * SLOT];
__device__ int   d_pidx[TOKS * 2];

// ---------------- helpers ----------------------------------------------------
__device__ __forceinline__ unsigned f2tf(float f) {
    unsigned u; asm("cvt.rna.tf32.f32 %0, %1;" : "=r"(u) : "f"(f)); return u;
}
__device__ __forceinline__ unsigned tfu(unsigned u) {
    unsigned o; asm("cvt.rna.tf32.f32 %0, %1;" : "=r"(o) : "f"(__uint_as_float(u))); return o;
}
__device__ __forceinline__ void mma8(float* c, const unsigned* a, const unsigned* b) {
    asm volatile(
        "mma.sync.aligned.m16n8k8.row.col.f32.tf32.tf32.f32 "
        "{%0,%1,%2,%3}, {%4,%5,%6,%7}, {%8,%9}, {%0,%1,%2,%3};"
        : "+f"(c[0]), "+f"(c[1]), "+f"(c[2]), "+f"(c[3])
        : "r"(a[0]), "r"(a[1]), "r"(a[2]), "r"(a[3]), "r"(b[0]), "r"(b[1]));
}
__device__ __forceinline__ void ldsm4(unsigned* r, unsigned addr) {
    asm volatile("ldmatrix.sync.aligned.m8n8.x4.shared.b16 {%0,%1,%2,%3}, [%4];"
        : "=r"(r[0]), "=r"(r[1]), "=r"(r[2]), "=r"(r[3]) : "r"(addr));
}
__device__ __forceinline__ void cpa(unsigned dst, const float* src) {
    asm volatile("cp.async.cg.shared.global [%0], [%1], 16;" :: "r"(dst), "l"(src));
}
#define CP_COMMIT asm volatile("cp.async.commit_group;")
#define CP_WAIT1  asm volatile("cp.async.wait_group 1;")

// ---------------- init / conv_x ---------------------------------------------
__global__ void init_kernel() {
    if (threadIdx.x < NEXP) d_count[threadIdx.x] = 0;
}
__global__ void convx_kernel(const float* __restrict__ x) {
    int i = (blockIdx.x * 256 + threadIdx.x) * 4;
    float4 v = *(const float4*)(x + i);
    float4 o;
    o.x = __uint_as_float(f2tf(v.x)); o.y = __uint_as_float(f2tf(v.y));
    o.z = __uint_as_float(f2tf(v.z)); o.w = __uint_as_float(f2tf(v.w));
    *(float4*)(d_xtf + i) = o;
}

// ---------------- routing ---------------------------------------------------
__global__ void routing_kernel(const float* __restrict__ x,
                               const float* __restrict__ gw) {
    int t = blockIdx.x;
    int tid = threadIdx.x;
    int w = tid >> 5, lane = tid & 31;
    __shared__ float lg[NEXP];

    const float* xr = x + (size_t)t * HDIM;
    const float* gr = gw + (size_t)w * HDIM;
    float s = 0.f;
    for (int i = lane * 4; i < HDIM; i += 128) {
        float4 a = *(const float4*)(xr + i);
        float4 b = *(const float4*)(gr + i);
        s += a.x * b.x + a.y * b.y + a.z * b.z + a.w * b.w;
    }
    #pragma unroll
    for (int o = 16; o; o >>= 1) s += __shfl_xor_sync(0xFFFFFFFFu, s, o);
    if (lane == 0) lg[w] = s;
    __syncthreads();

    if (tid == 0) {
        float l[NEXP];
        #pragma unroll
        for (int e = 0; e < NEXP; e++) l[e] = lg[e];

        int s1 = 0;
        for (int e = 1; e < NEXP; e++) if (l[e] > l[s1]) s1 = e;
        float m1 = l[s1];
        int s2 = (s1 == 0) ? 1 : 0;
        for (int e = 0; e < NEXP; e++) { if (e == s1) continue; if (l[e] > l[s2]) s2 = e; }
        float m2 = l[s2];

        float mult1, mult2;
        {
            float keep[NEXP]; float mx = -1e30f;
            for (int e = 0; e < NEXP; e++) {
                float f = fmaxf(fabsf(l[e]), m1);
                keep[e] = ((m1 - l[e]) / f > 0.02f) ? -1e30f : l[e];
                mx = fmaxf(mx, keep[e]);
            }
            float sum = 0.f, num = 0.f;
            for (int e = 0; e < NEXP; e++) {
                float p = (keep[e] <= -1e30f) ? 0.f : expf(keep[e] - mx);
                sum += p; if (e == s1) num = p;
            }
            mult1 = num / sum;
        }
        {
            float keep[NEXP]; float mx = -1e30f;
            for (int e = 0; e < NEXP; e++) {
                float f = fmaxf(fabsf(l[e]), m2);
                bool msk = ((m2 - l[e]) / f > 0.02f) || (e == s1);
                keep[e] = msk ? -1e30f : l[e];
                mx = fmaxf(mx, keep[e]);
            }
            float sum = 0.f, num = 0.f;
            for (int e = 0; e < NEXP; e++) {
                float p = (keep[e] <= -1e30f) ? 0.f : expf(keep[e] - mx);
                sum += p; if (e == s2) num = p;
            }
            mult2 = num / sum;
        }

        int p = atomicAdd(&d_count[s1], 1);
        d_tok[s1 * SLOT + p] = t; d_mult[s1 * SLOT + p] = mult1;
        d_pidx[t * 2 + 0] = s1 * SLOT + p;
        p = atomicAdd(&d_count[s2], 1);
        d_tok[s2 * SLOT + p] = t; d_mult[s2 * SLOT + p] = mult2;
        d_pidx[t * 2 + 1] = s2 * SLOT + p;
    }
}

// ---------------- GEMM1: 64x64 tile, fused w1/w3, ldmatrix fragments --------
__global__ __launch_bounds__(256) void gemm1_kernel(const float* __restrict__ w1,
                                                    const float* __restrict__ w3) {
    extern __shared__ float sm[];
    float* As  = sm;                  // 3 * BSTG_F
    float* B1s = sm + 3 * BSTG_F;
    float* B3s = sm + 6 * BSTG_F;

    int e = blockIdx.y >> 3, mtile = blockIdx.y & 7;
    int cnt = d_count[e];
    int m0 = mtile * 64;
    if (m0 >= cnt) return;
    int n0 = blockIdx.x * 64;

    int tid = threadIdx.x;
    // cp.async assignments: 2 float4 per thread per 64-row tile
    const float* aptr[2]; const float* b1ptr[2]; const float* b3ptr[2];
    unsigned soff[2];
    #pragma unroll
    for (int j = 0; j < 2; j++) {
        int gidx = tid + 256 * j;
        int row = gidx >> 3, c4 = gidx & 7;
        int r = m0 + row; if (r >= cnt) r = cnt - 1;
        aptr[j]  = d_xtf + (size_t)d_tok[e * SLOT + r] * HDIM + c4 * 4;
        b1ptr[j] = w1 + ((size_t)e * FDIM + n0 + row) * HDIM + c4 * 4;
        b3ptr[j] = w3 + ((size_t)e * FDIM + n0 + row) * HDIM + c4 * 4;
        soff[j]  = (unsigned)(row * SST + c4 * 4) * 4;
    }

    unsigned sA  = (unsigned)__cvta_generic_to_shared(As);
    unsigned sB1 = (unsigned)__cvta_generic_to_shared(B1s);
    unsigned sB3 = (unsigned)__cvta_generic_to_shared(B3s);

    const int NKT = HDIM / 32;  // 32

    #pragma unroll
    for (int s = 0; s < 2; s++) {
        int ko = s * 32;
        unsigned so = (unsigned)s * (BSTG_F * 4);
        #pragma unroll
        for (int j = 0; j < 2; j++) {
            cpa(sA  + so + soff[j], aptr[j]  + ko);
            cpa(sB1 + so + soff[j], b1ptr[j] + ko);
            cpa(sB3 + so + soff[j], b3ptr[j] + ko);
        }
        CP_COMMIT;
    }

    int warp = tid >> 5, lane = tid & 31;
    int wm = warp >> 2, wn = warp & 3;     // 2 x 4 warps, warp tile 32x16
    int g = lane >> 2, tg = lane & 3;
    int sub = lane >> 3, lrow = lane & 7;

    // ldmatrix per-thread byte offsets (relative to stage base)
    unsigned aoffm[2], boff;
    #pragma unroll
    for (int mi = 0; mi < 2; mi++)
        aoffm[mi] = (unsigned)((wm * 32 + mi * 16 + (sub & 1) * 8 + lrow) * SST + (sub >> 1) * 4) * 4;
    boff = (unsigned)((wn * 16 + (sub >> 1) * 8 + lrow) * SST + (sub & 1) * 4) * 4;

    float acc1[2][2][4] = {}, acc3[2][2][4] = {};

    for (int kt = 0; kt < NKT; kt++) {
        CP_WAIT1;
        __syncthreads();
        int kn = kt + 2;
        if (kn < NKT) {
            int ko = kn * 32;
            unsigned so = (unsigned)(kn % 3) * (BSTG_F * 4);
            #pragma unroll
            for (int j = 0; j < 2; j++) {
                cpa(sA  + so + soff[j], aptr[j]  + ko);
                cpa(sB1 + so + soff[j], b1ptr[j] + ko);
                cpa(sB3 + so + soff[j], b3ptr[j] + ko);
            }
        }
        CP_COMMIT;

        unsigned sAc  = sA  + (unsigned)(kt % 3) * (BSTG_F * 4);
        unsigned sB1c = sB1 + (unsigned)(kt % 3) * (BSTG_F * 4);
        unsigned sB3c = sB3 + (unsigned)(kt % 3) * (BSTG_F * 4);

        #pragma unroll
        for (int ks = 0; ks < 4; ks++) {
            unsigned kb = (unsigned)ks * 32;   // 8 floats
            unsigned af[2][4], b1r[4], b3r[4];
            ldsm4(af[0], sAc + aoffm[0] + kb);
            ldsm4(af[1], sAc + aoffm[1] + kb);
            ldsm4(b1r, sB1c + boff + kb);
            ldsm4(b3r, sB3c + boff + kb);
            #pragma unroll
            for (int j = 0; j < 4; j++) { b1r[j] = tfu(b1r[j]); b3r[j] = tfu(b3r[j]); }
            #pragma unroll
            for (int ni = 0; ni < 2; ni++)
            #pragma unroll
            for (int mi = 0; mi < 2; mi++) {
                mma8(acc1[mi][ni], af[mi], &b1r[ni * 2]);
                mma8(acc3[mi][ni], af[mi], &b3r[ni * 2]);
            }
        }
    }

    // epilogue: silu(s1) * s3, tf32-rounded, -> d_h
    #pragma unroll
    for (int mi = 0; mi < 2; mi++)
    #pragma unroll
    for (int ni = 0; ni < 2; ni++)
    #pragma unroll
    for (int h = 0; h < 2; h++) {
        int lr = wm * 32 + mi * 16 + g + h * 8;
        if (m0 + lr < cnt) {
            int col = n0 + wn * 16 + ni * 8 + tg * 2;
            float v1a = acc1[mi][ni][h * 2], v1b = acc1[mi][ni][h * 2 + 1];
            float v3a = acc3[mi][ni][h * 2], v3b = acc3[mi][ni][h * 2 + 1];
            float h0 = v1a * v3a / (1.f + __expf(-v1a));
            float h1 = v1b * v3b / (1.f + __expf(-v1b));
            float2 o;
            o.x = __uint_as_float(f2tf(h0));
            o.y = __uint_as_float(f2tf(h1));
            *(float2*)&d_h[((size_t)(e * SLOT + m0 + lr)) * FDIM + col] = o;
        }
    }
}

// ---------------- GEMM2: 128x64 tile, split-K x2, ldmatrix fragments --------
__global__ __launch_bounds__(256) void gemm2_kernel(const float* __restrict__ w2) {
    extern __shared__ float sm[];
    float* As = sm;                   // 3 * ASTG_F
    float* Bs = sm + 3 * ASTG_F;      // 3 * BSTG_F

    int e = blockIdx.y >> 2, mtile = blockIdx.y & 3;
    int cnt = d_count[e];
    int m0 = mtile * 128;
    if (m0 >= cnt) return;
    int n0 = blockIdx.x * 64;
    int kz = blockIdx.z;
    int kbase = kz * (FDIM / 2);

    int tid = threadIdx.x;
    const float* aptr[4]; unsigned asoff[4];
    #pragma unroll
    for (int j = 0; j < 4; j++) {
        int gidx = tid + 256 * j;
        int row = gidx >> 3, c4 = gidx & 7;
        int r = m0 + row; if (r >= cnt) r = cnt - 1;
        aptr[j]  = d_h + ((size_t)(e * SLOT) + r) * FDIM + kbase + c4 * 4;
        asoff[j] = (unsigned)(row * SST + c4 * 4) * 4;
    }
    const float* bptr[2]; unsigned bsoff[2];
    #pragma unroll
    for (int j = 0; j < 2; j++) {
        int gidx = tid + 256 * j;
        int row = gidx >> 3, c4 = gidx & 7;
        bptr[j]  = w2 + ((size_t)e * HDIM + n0 + row) * FDIM + kbase + c4 * 4;
        bsoff[j] = (unsigned)(row * SST + c4 * 4) * 4;
    }

    unsigned sA = (unsigned)__cvta_generic_to_shared(As);
    unsigned sB = (unsigned)__cvta_generic_to_shared(Bs);

    const int NKT = (FDIM / 2) / 32;  // 64

    #pragma unroll
    for (int s = 0; s < 2; s++) {
        int ko = s * 32;
        unsigned soA = (unsigned)s * (ASTG_F * 4);
        unsigned soB = (unsigned)s * (BSTG_F * 4);
        #pragma unroll
        for (int j = 0; j < 4; j++) cpa(sA + soA + asoff[j], aptr[j] + ko);
        #pragma unroll
        for (int j = 0; j < 2; j++) cpa(sB + soB + bsoff[j], bptr[j] + ko);
        CP_COMMIT;
    }

    int warp = tid >> 5, lane = tid & 31;
    int wm = warp >> 1, wn = warp & 1;     // 4 x 2 warps, warp tile 32x32
    int g = lane >> 2, tg = lane & 3;
    int sub = lane >> 3, lrow = lane & 7;

    unsigned aoffm[2], boffp[2];
    #pragma unroll
    for (int mi = 0; mi < 2; mi++)
        aoffm[mi] = (unsigned)((wm * 32 + mi * 16 + (sub & 1) * 8 + lrow) * SST + (sub >> 1) * 4) * 4;
    #pragma unroll
    for (int p = 0; p < 2; p++)
        boffp[p] = (unsigned)((wn * 32 + p * 16 + (sub >> 1) * 8 + lrow) * SST + (sub & 1) * 4) * 4;

    float acc[2][4][4] = {};

    for (int kt = 0; kt < NKT; kt++) {
        CP_WAIT1;
        __syncthreads();
        int kn = kt + 2;
        if (kn < NKT) {
            int ko = kn * 32;
            unsigned soA = (unsigned)(kn % 3) * (ASTG_F * 4);
            unsigned soB = (unsigned)(kn % 3) * (BSTG_F * 4);
            #pragma unroll
            for (int j = 0; j < 4; j++) cpa(sA + soA + asoff[j], aptr[j] + ko);
            #pragma unroll
            for (int j = 0; j < 2; j++) cpa(sB + soB + bsoff[j], bptr[j] + ko);
        }
        CP_COMMIT;

        unsigned sAc = sA + (unsigned)(kt % 3) * (ASTG_F * 4);
        unsigned sBc = sB + (unsigned)(kt % 3) * (BSTG_F * 4);

        #pragma unroll
        for (int ks = 0; ks < 4; ks++) {
            unsigned kb = (unsigned)ks * 32;
            unsigned af[2][4], br[2][4];
            ldsm4(af[0], sAc + aoffm[0] + kb);
            ldsm4(af[1], sAc + aoffm[1] + kb);
            ldsm4(br[0], sBc + boffp[0] + kb);
            ldsm4(br[1], sBc + boffp[1] + kb);
            #pragma unroll
            for (int p = 0; p < 2; p++)
            #pragma unroll
            for (int j = 0; j < 4; j++) br[p][j] = tfu(br[p][j]);
            #pragma unroll
            for (int p = 0; p < 2; p++)
            #pragma unroll
            for (int hn = 0; hn < 2; hn++) {
                int ni = p * 2 + hn;
                #pragma unroll
                for (int mi = 0; mi < 2; mi++)
                    mma8(acc[mi][ni], af[mi], &br[p][hn * 2]);
            }
        }
    }

    float* po = d_po2 + (size_t)kz * (NEXP * SLOT * HDIM);
    #pragma unroll
    for (int mi = 0; mi < 2; mi++)
    #pragma unroll
    for (int ni = 0; ni < 4; ni++)
    #pragma unroll
    for (int h = 0; h < 2; h++) {
        int lr = wm * 32 + mi * 16 + g + h * 8;
        if (m0 + lr < cnt) {
            float mult = d_mult[e * SLOT + m0 + lr];
            int col = n0 + wn * 32 + ni * 8 + tg * 2;
            float2 o;
            o.x = acc[mi][ni][h * 2]     * mult;
            o.y = acc[mi][ni][h * 2 + 1] * mult;
            *(float2*)&po[((size_t)(e * SLOT + m0 + lr)) * HDIM + col] = o;
        }
    }
}

// ---------------- finalize ---------------------------------------------------
__global__ void finalize_kernel(float* __restrict__ out) {
    int t = blockIdx.x;
    int i = threadIdx.x;
    int p0 = d_pidx[t * 2], p1 = d_pidx[t * 2 + 1];
    const float* po0 = d_po2;
    const float* po1 = d_po2 + (size_t)(NEXP * SLOT * HDIM);
    float4 a = ((const float4*)(po0 + (size_t)p0 * HDIM))[i];
    float4 b = ((const float4*)(po0 + (size_t)p1 * HDIM))[i];
    float4 c = ((const float4*)(po1 + (size_t)p0 * HDIM))[i];
    float4 d = ((const float4*)(po1 + (size_t)p1 * HDIM))[i];
    float4 o;
    o.x = (a.x + c.x) + (b.x + d.x);
    o.y = (a.y + c.y) + (b.y + d.y);
    o.z = (a.z + c.z) + (b.z + d.z);
    o.w = (a.w + c.w) + (b.w + d.w);
    ((float4*)(out + (size_t)t * HDIM))[i] = o;
}

// ---------------- launch ----------------------------------------------------
extern "C" void kernel_launch(void* const* d_in, const int* in_sizes, int n_in,
                              void* d_out, int out_size) {
    const float* x  = (const float*)d_in[0];
    const float* gw = (const float*)d_in[1];
    const float* w1 = (const float*)d_in[2];
    const float* w2 = (const float*)d_in[3];
    const float* w3 = (const float*)d_in[4];
    float* out = (float*)d_out;

    const int smem1 = 9 * BSTG_F * 4;                    // 82944 B
    const int smem2 = (3 * ASTG_F + 3 * BSTG_F) * 4;     // 82944 B
    cudaFuncSetAttribute(gemm1_kernel, cudaFuncAttributeMaxDynamicSharedMemorySize, smem1);
    cudaFuncSetAttribute(gemm2_kernel, cudaFuncAttributeMaxDynamicSharedMemorySize, smem2);

    init_kernel<<<1, 32>>>();
    convx_kernel<<<TOKS * HDIM / 1024, 256>>>(x);
    routing_kernel<<<TOKS, 256>>>(x, gw);
    gemm1_kernel<<<dim3(FDIM / 64, NEXP * 8), 256, smem1>>>(w1, w3);
    gemm2_kernel<<<dim3(HDIM / 64, NEXP * 4, 2), 256, smem2>>>(w2);
    finalize_kernel<<<TOKS, 256>>>(out);
}

// round 5
// speedup vs baseline: 1.2475x; 1.2475x over previous
#include <cuda_runtime.h>
#include <cuda_fp16.h>
#include <cstdint>
#include <math.h>

#define TOKS 512
#define HDIM 1024
#define FDIM 4096
#define NEXP 8
#define SLOT 512
#define SSTH 40                    // halves per smem row (80 B, ldsm conflict-free)
#define ROWH64  (64 * SSTH)        // 2560 halves per 64-row stage
#define ROWH128 (128 * SSTH)       // 5120 halves per 128-row stage

// ---------------- scratch (static device globals) ---------------------------
__device__ __half d_xh[TOKS * HDIM];               // fp16 x (1 MB)
__device__ __half d_h[NEXP * SLOT * FDIM];         // fp16 intermediate h (32 MB)
__device__ float  d_po2[2 * NEXP * SLOT * HDIM];   // split-K partials (fp32)
__device__ int    d_count[NEXP];
__device__ int    d_tok[NEXP * SLOT];
__device__ float  d_mult[NEXP * SLOT];
__device__ int    d_pidx[TOKS * 2];

// ---------------- helpers ----------------------------------------------------
__device__ __forceinline__ unsigned pk2(float a, float b) {
    __half2 h = __floats2half2_rn(a, b);
    return *(unsigned*)&h;
}
__device__ __forceinline__ void mma16(float* c, const unsigned* a, const unsigned* b) {
    asm volatile(
        "mma.sync.aligned.m16n8k16.row.col.f32.f16.f16.f32 "
        "{%0,%1,%2,%3}, {%4,%5,%6,%7}, {%8,%9}, {%0,%1,%2,%3};"
        : "+f"(c[0]), "+f"(c[1]), "+f"(c[2]), "+f"(c[3])
        : "r"(a[0]), "r"(a[1]), "r"(a[2]), "r"(a[3]), "r"(b[0]), "r"(b[1]));
}
__device__ __forceinline__ void ldsm4(unsigned* r, unsigned addr) {
    asm volatile("ldmatrix.sync.aligned.m8n8.x4.shared.b16 {%0,%1,%2,%3}, [%4];"
        : "=r"(r[0]), "=r"(r[1]), "=r"(r[2]), "=r"(r[3]) : "r"(addr));
}
__device__ __forceinline__ void cpa(unsigned dst, const void* src) {
    asm volatile("cp.async.cg.shared.global [%0], [%1], 16;" :: "r"(dst), "l"(src));
}
#define CP_COMMIT asm volatile("cp.async.commit_group;")
#define CP_WAIT2  asm volatile("cp.async.wait_group 2;")

// ---------------- init / convx ----------------------------------------------
__global__ void init_kernel() {
    if (threadIdx.x < NEXP) d_count[threadIdx.x] = 0;
}
__global__ void convx_kernel(const float* __restrict__ x) {
    int i = (blockIdx.x * 256 + threadIdx.x) * 4;
    float4 v = *(const float4*)(x + i);
    uint2 o; o.x = pk2(v.x, v.y); o.y = pk2(v.z, v.w);
    *(uint2*)&d_xh[i] = o;
}

// ---------------- routing ---------------------------------------------------
__global__ void routing_kernel(const float* __restrict__ x,
                               const float* __restrict__ gw) {
    int t = blockIdx.x;
    int tid = threadIdx.x;
    int w = tid >> 5, lane = tid & 31;
    __shared__ float lg[NEXP];

    const float* xr = x + (size_t)t * HDIM;
    const float* gr = gw + (size_t)w * HDIM;
    float s = 0.f;
    for (int i = lane * 4; i < HDIM; i += 128) {
        float4 a = *(const float4*)(xr + i);
        float4 b = *(const float4*)(gr + i);
        s += a.x * b.x + a.y * b.y + a.z * b.z + a.w * b.w;
    }
    #pragma unroll
    for (int o = 16; o; o >>= 1) s += __shfl_xor_sync(0xFFFFFFFFu, s, o);
    if (lane == 0) lg[w] = s;
    __syncthreads();

    if (tid == 0) {
        float l[NEXP];
        #pragma unroll
        for (int e = 0; e < NEXP; e++) l[e] = lg[e];

        int s1 = 0;
        for (int e = 1; e < NEXP; e++) if (l[e] > l[s1]) s1 = e;
        float m1 = l[s1];
        int s2 = (s1 == 0) ? 1 : 0;
        for (int e = 0; e < NEXP; e++) { if (e == s1) continue; if (l[e] > l[s2]) s2 = e; }
        float m2 = l[s2];

        float mult1, mult2;
        {
            float keep[NEXP]; float mx = -1e30f;
            for (int e = 0; e < NEXP; e++) {
                float f = fmaxf(fabsf(l[e]), m1);
                keep[e] = ((m1 - l[e]) / f > 0.02f) ? -1e30f : l[e];
                mx = fmaxf(mx, keep[e]);
            }
            float sum = 0.f, num = 0.f;
            for (int e = 0; e < NEXP; e++) {
                float p = (keep[e] <= -1e30f) ? 0.f : expf(keep[e] - mx);
                sum += p; if (e == s1) num = p;
            }
            mult1 = num / sum;
        }
        {
            float keep[NEXP]; float mx = -1e30f;
            for (int e = 0; e < NEXP; e++) {
                float f = fmaxf(fabsf(l[e]), m2);
                bool msk = ((m2 - l[e]) / f > 0.02f) || (e == s1);
                keep[e] = msk ? -1e30f : l[e];
                mx = fmaxf(mx, keep[e]);
            }
            float sum = 0.f, num = 0.f;
            for (int e = 0; e < NEXP; e++) {
                float p = (keep[e] <= -1e30f) ? 0.f : expf(keep[e] - mx);
                sum += p; if (e == s2) num = p;
            }
            mult2 = num / sum;
        }

        int p = atomicAdd(&d_count[s1], 1);
        d_tok[s1 * SLOT + p] = t; d_mult[s1 * SLOT + p] = mult1;
        d_pidx[t * 2 + 0] = s1 * SLOT + p;
        p = atomicAdd(&d_count[s2], 1);
        d_tok[s2 * SLOT + p] = t; d_mult[s2 * SLOT + p] = mult2;
        d_pidx[t * 2 + 1] = s2 * SLOT + p;
    }
}

// ---------------- GEMM1: 64x64 tile, fused w1/w3, fp16 mma ------------------
// smem: A ring-4 (fp16, cp.async from d_xh) + B1/B3 double buf (LDG fp32 -> cvt)
__global__ __launch_bounds__(256, 3) void gemm1_kernel(const float* __restrict__ w1,
                                                       const float* __restrict__ w3) {
    extern __shared__ __half smh[];
    __half* Ab  = smh;                       // 4 * ROWH64
    __half* B1b = smh + 4 * ROWH64;          // 2 * ROWH64
    __half* B3b = smh + 6 * ROWH64;          // 2 * ROWH64

    int e = blockIdx.y >> 3, mtile = blockIdx.y & 7;
    int cnt = d_count[e];
    int m0 = mtile * 64;
    if (m0 >= cnt) return;
    int n0 = blockIdx.x * 64;

    int tid = threadIdx.x;
    // A cp.async: thread -> (row = tid>>2, 16B chunk = tid&3)
    int arow = tid >> 2, ac = tid & 3;
    int rr = m0 + arow; if (rr >= cnt) rr = cnt - 1;
    const __half* aptr = d_xh + (size_t)d_tok[e * SLOT + rr] * HDIM + ac * 8;
    unsigned aoffs = (unsigned)(arow * SSTH + ac * 8) * 2;

    // B LDG: thread -> (row = tid>>2, 8 floats at (tid&3)*8)
    const float* b1p = w1 + ((size_t)e * FDIM + n0 + arow) * HDIM + ac * 8;
    const float* b3p = w3 + ((size_t)e * FDIM + n0 + arow) * HDIM + ac * 8;
    unsigned bsts = (unsigned)(arow * SSTH + ac * 8) * 2;

    unsigned uA  = (unsigned)__cvta_generic_to_shared(Ab);
    unsigned uB1 = (unsigned)__cvta_generic_to_shared(B1b);
    unsigned uB3 = (unsigned)__cvta_generic_to_shared(B3b);

    const int NKT = HDIM / 32;  // 32

    // prologue: B regs for kt=0; A stages 0,1,2
    float4 pb1a = *(const float4*)b1p, pb1b = *(const float4*)(b1p + 4);
    float4 pb3a = *(const float4*)b3p, pb3b = *(const float4*)(b3p + 4);
    #pragma unroll
    for (int s = 0; s < 3; s++) {
        cpa(uA + (unsigned)s * (ROWH64 * 2) + aoffs, aptr + s * 32);
        CP_COMMIT;
    }

    int warp = tid >> 5, lane = tid & 31;
    int wm = warp >> 2, wn = warp & 3;     // 2 x 4 warps, warp tile 32x16
    int g = lane >> 2, tg = lane & 3;

    // ldsm offsets (bytes, relative to stage base)
    unsigned aoffm[2], boff;
    #pragma unroll
    for (int mi = 0; mi < 2; mi++)
        aoffm[mi] = (unsigned)((wm * 32 + mi * 16 + (lane & 7) + ((lane >> 3) & 1) * 8) * SSTH
                               + (lane >> 4) * 8) * 2;
    boff = (unsigned)((wn * 16 + (lane & 7) + ((lane >> 4) & 1) * 8) * SSTH
                      + ((lane >> 3) & 1) * 8) * 2;

    float acc1[2][2][4] = {}, acc3[2][2][4] = {};

    for (int kt = 0; kt < NKT; kt++) {
        // convert+store this k-tile's weights (regs loaded one tile ago)
        unsigned bso = (unsigned)(kt & 1) * (ROWH64 * 2) + bsts;
        { uint4 u; u.x = pk2(pb1a.x, pb1a.y); u.y = pk2(pb1a.z, pb1a.w);
          u.z = pk2(pb1b.x, pb1b.y); u.w = pk2(pb1b.z, pb1b.w);
          *(uint4*)((char*)B1b + ((kt & 1) * (ROWH64 * 2) + bsts)) = u; }
        { uint4 u; u.x = pk2(pb3a.x, pb3a.y); u.y = pk2(pb3a.z, pb3a.w);
          u.z = pk2(pb3b.x, pb3b.y); u.w = pk2(pb3b.z, pb3b.w);
          *(uint4*)((char*)B3b + ((kt & 1) * (ROWH64 * 2) + bsts)) = u; }
        (void)bso;
        CP_WAIT2;
        __syncthreads();

        if (kt + 1 < NKT) {
            const float* p1 = b1p + (kt + 1) * 32;
            const float* p3 = b3p + (kt + 1) * 32;
            pb1a = *(const float4*)p1; pb1b = *(const float4*)(p1 + 4);
            pb3a = *(const float4*)p3; pb3b = *(const float4*)(p3 + 4);
        }
        if (kt + 3 < NKT)
            cpa(uA + (unsigned)((kt + 3) & 3) * (ROWH64 * 2) + aoffs, aptr + (kt + 3) * 32);
        CP_COMMIT;

        unsigned sAc  = uA  + (unsigned)(kt & 3) * (ROWH64 * 2);
        unsigned sB1c = uB1 + (unsigned)(kt & 1) * (ROWH64 * 2);
        unsigned sB3c = uB3 + (unsigned)(kt & 1) * (ROWH64 * 2);

        #pragma unroll
        for (int ks = 0; ks < 2; ks++) {
            unsigned kb = (unsigned)ks * 32;   // 16 halves
            unsigned af[2][4], b1r[4], b3r[4];
            ldsm4(af[0], sAc + aoffm[0] + kb);
            ldsm4(af[1], sAc + aoffm[1] + kb);
            ldsm4(b1r, sB1c + boff + kb);
            ldsm4(b3r, sB3c + boff + kb);
            #pragma unroll
            for (int ni = 0; ni < 2; ni++)
            #pragma unroll
            for (int mi = 0; mi < 2; mi++) {
                mma16(acc1[mi][ni], af[mi], &b1r[ni * 2]);
                mma16(acc3[mi][ni], af[mi], &b3r[ni * 2]);
            }
        }
    }

    // epilogue: silu(s1) * s3 -> d_h (fp16)
    #pragma unroll
    for (int mi = 0; mi < 2; mi++)
    #pragma unroll
    for (int ni = 0; ni < 2; ni++)
    #pragma unroll
    for (int h = 0; h < 2; h++) {
        int lr = wm * 32 + mi * 16 + g + h * 8;
        if (m0 + lr < cnt) {
            int col = n0 + wn * 16 + ni * 8 + tg * 2;
            float v1a = acc1[mi][ni][h * 2], v1b = acc1[mi][ni][h * 2 + 1];
            float v3a = acc3[mi][ni][h * 2], v3b = acc3[mi][ni][h * 2 + 1];
            float h0 = v1a * v3a / (1.f + __expf(-v1a));
            float h1 = v1b * v3b / (1.f + __expf(-v1b));
            unsigned u = pk2(h0, h1);
            *(unsigned*)&d_h[((size_t)(e * SLOT + m0 + lr)) * FDIM + col] = u;
        }
    }
}

// ---------------- GEMM2: 128x64 tile, split-K x2, fp16 mma ------------------
__global__ __launch_bounds__(256, 3) void gemm2_kernel(const float* __restrict__ w2) {
    extern __shared__ __half smh[];
    __half* Ab = smh;                       // 4 * ROWH128
    __half* Bb = smh + 4 * ROWH128;         // 2 * ROWH64

    int e = blockIdx.y >> 2, mtile = blockIdx.y & 3;
    int cnt = d_count[e];
    int m0 = mtile * 128;
    if (m0 >= cnt) return;
    int n0 = blockIdx.x * 64;
    int kz = blockIdx.z;
    int kbase = kz * (FDIM / 2);

    int tid = threadIdx.x;
    // A cp.async: 2 chunks/thread (128 rows x 4 chunks)
    const __half* aptr[2]; unsigned aoffs[2];
    #pragma unroll
    for (int j = 0; j < 2; j++) {
        int gidx = tid + 256 * j;
        int row = gidx >> 2, c = gidx & 3;
        int rr = m0 + row; if (rr >= cnt) rr = cnt - 1;
        aptr[j]  = d_h + ((size_t)(e * SLOT) + rr) * FDIM + kbase + c * 8;
        aoffs[j] = (unsigned)(row * SSTH + c * 8) * 2;
    }
    // B LDG: row = tid>>2, 8 floats
    int brow = tid >> 2, bc = tid & 3;
    const float* bp = w2 + ((size_t)e * HDIM + n0 + brow) * FDIM + kbase + bc * 8;
    unsigned bsts = (unsigned)(brow * SSTH + bc * 8) * 2;

    unsigned uA = (unsigned)__cvta_generic_to_shared(Ab);

    const int NKT = (FDIM / 2) / 32;  // 64

    float4 pba = *(const float4*)bp, pbb = *(const float4*)(bp + 4);
    #pragma unroll
    for (int s = 0; s < 3; s++) {
        #pragma unroll
        for (int j = 0; j < 2; j++)
            cpa(uA + (unsigned)s * (ROWH128 * 2) + aoffs[j], aptr[j] + s * 32);
        CP_COMMIT;
    }

    int warp = tid >> 5, lane = tid & 31;
    int wm = warp >> 1, wn = warp & 1;     // 4 x 2 warps, warp tile 32x32
    int g = lane >> 2, tg = lane & 3;

    unsigned aoffm[2], boffp[2];
    #pragma unroll
    for (int mi = 0; mi < 2; mi++)
        aoffm[mi] = (unsigned)((wm * 32 + mi * 16 + (lane & 7) + ((lane >> 3) & 1) * 8) * SSTH
                               + (lane >> 4) * 8) * 2;
    #pragma unroll
    for (int p = 0; p < 2; p++)
        boffp[p] = (unsigned)((wn * 32 + p * 16 + (lane & 7) + ((lane >> 4) & 1) * 8) * SSTH
                              + ((lane >> 3) & 1) * 8) * 2;

    float acc[2][4][4] = {};

    for (int kt = 0; kt < NKT; kt++) {
        { uint4 u; u.x = pk2(pba.x, pba.y); u.y = pk2(pba.z, pba.w);
          u.z = pk2(pbb.x, pbb.y); u.w = pk2(pbb.z, pbb.w);
          *(uint4*)((char*)Bb + ((kt & 1) * (ROWH64 * 2) + bsts)) = u; }
        CP_WAIT2;
        __syncthreads();

        if (kt + 1 < NKT) {
            const float* p = bp + (kt + 1) * 32;
            pba = *(const float4*)p; pbb = *(const float4*)(p + 4);
        }
        if (kt + 3 < NKT) {
            #pragma unroll
            for (int j = 0; j < 2; j++)
                cpa(uA + (unsigned)((kt + 3) & 3) * (ROWH128 * 2) + aoffs[j], aptr[j] + (kt + 3) * 32);
        }
        CP_COMMIT;

        unsigned sAc = uA + (unsigned)(kt & 3) * (ROWH128 * 2);
        unsigned sBc = (unsigned)__cvta_generic_to_shared(Bb) + (unsigned)(kt & 1) * (ROWH64 * 2);

        #pragma unroll
        for (int ks = 0; ks < 2; ks++) {
            unsigned kb = (unsigned)ks * 32;
            unsigned af[2][4], br[2][4];
            ldsm4(af[0], sAc + aoffm[0] + kb);
            ldsm4(af[1], sAc + aoffm[1] + kb);
            ldsm4(br[0], sBc + boffp[0] + kb);
            ldsm4(br[1], sBc + boffp[1] + kb);
            #pragma unroll
            for (int p = 0; p < 2; p++)
            #pragma unroll
            for (int hn = 0; hn < 2; hn++) {
                int ni = p * 2 + hn;
                #pragma unroll
                for (int mi = 0; mi < 2; mi++)
                    mma16(acc[mi][ni], af[mi], &br[p][hn * 2]);
            }
        }
    }

    float* po = d_po2 + (size_t)kz * (NEXP * SLOT * HDIM);
    #pragma unroll
    for (int mi = 0; mi < 2; mi++)
    #pragma unroll
    for (int ni = 0; ni < 4; ni++)
    #pragma unroll
    for (int h = 0; h < 2; h++) {
        int lr = wm * 32 + mi * 16 + g + h * 8;
        if (m0 + lr < cnt) {
            float mult = d_mult[e * SLOT + m0 + lr];
            int col = n0 + wn * 32 + ni * 8 + tg * 2;
            float2 o;
            o.x = acc[mi][ni][h * 2]     * mult;
            o.y = acc[mi][ni][h * 2 + 1] * mult;
            *(float2*)&po[((size_t)(e * SLOT + m0 + lr)) * HDIM + col] = o;
        }
    }
}

// ---------------- finalize ---------------------------------------------------
__global__ void finalize_kernel(float* __restrict__ out) {
    int t = blockIdx.x;
    int i = threadIdx.x;
    int p0 = d_pidx[t * 2], p1 = d_pidx[t * 2 + 1];
    const float* po0 = d_po2;
    const float* po1 = d_po2 + (size_t)(NEXP * SLOT * HDIM);
    float4 a = ((const float4*)(po0 + (size_t)p0 * HDIM))[i];
    float4 b = ((const float4*)(po0 + (size_t)p1 * HDIM))[i];
    float4 c = ((const float4*)(po1 + (size_t)p0 * HDIM))[i];
    float4 d = ((const float4*)(po1 + (size_t)p1 * HDIM))[i];
    float4 o;
    o.x = (a.x + c.x) + (b.x + d.x);
    o.y = (a.y + c.y) + (b.y + d.y);
    o.z = (a.z + c.z) + (b.z + d.z);
    o.w = (a.w + c.w) + (b.w + d.w);
    ((float4*)(out + (size_t)t * HDIM))[i] = o;
}

// ---------------- launch ----------------------------------------------------
extern "C" void kernel_launch(void* const* d_in, const int* in_sizes, int n_in,
                              void* d_out, int out_size) {
    const float* x  = (const float*)d_in[0];
    const float* gw = (const float*)d_in[1];
    const float* w1 = (const float*)d_in[2];
    const float* w2 = (const float*)d_in[3];
    const float* w3 = (const float*)d_in[4];
    float* out = (float*)d_out;

    const int smem1 = 8 * ROWH64 * 2;                    // 40960 B
    const int smem2 = (4 * ROWH128 + 2 * ROWH64) * 2;    // 51200 B
    cudaFuncSetAttribute(gemm1_kernel, cudaFuncAttributeMaxDynamicSharedMemorySize, smem1);
    cudaFuncSetAttribute(gemm2_kernel, cudaFuncAttributeMaxDynamicSharedMemorySize, smem2);

    init_kernel<<<1, 32>>>();
    convx_kernel<<<TOKS * HDIM / 1024, 256>>>(x);
    routing_kernel<<<TOKS, 256>>>(x, gw);
    gemm1_kernel<<<dim3(FDIM / 64, NEXP * 8), 256, smem1>>>(w1, w3);
    gemm2_kernel<<<dim3(HDIM / 64, NEXP * 4, 2), 256, smem2>>>(w2);
    finalize_kernel<<<TOKS, 256>>>(out);
}